// round 3
// baseline (speedup 1.0000x reference)
#include <cuda_runtime.h>

#define NB     256
#define NQ     1000
#define NC     81
#define QCN    81000
#define TOPK   100
#define CAP    4096
#define NSAMP  2048
#define NTA    256
#define NTB    256
#define NTC    512
#define QPB    40      // queries per B-block
#define SPLITB 25      // 25*40 = 1000 queries
#define SORTN  512
#define CLO    100
#define CHI    500

// ---- global scratch (no allocs allowed) --------------------------------
__device__ float               g_w1[NB * NQ];
__device__ float               g_w2[NB * NQ];
__device__ float               g_lthr[NB * NQ];
__device__ float               g_thr[NB];
__device__ unsigned long long  g_cand[NB * CAP];
__device__ int                 g_cnt[NB];

__device__ __forceinline__ float sigf(float x) {
    return __fdividef(1.0f, 1.0f + __expf(-x));
}

__device__ __forceinline__ void pushg(int b, unsigned long long key) {
    unsigned m = __activemask();
    int lane   = threadIdx.x & 31;
    int leader = __ffs(m) - 1;
    int rank   = __popc(m & ((1u << lane) - 1u));
    int base   = 0;
    if (lane == leader) base = atomicAdd(&g_cnt[b], __popc(m));
    base = __shfl_sync(m, base, leader);
    int pos = base + rank;
    if (pos < CAP) g_cand[b * CAP + pos] = key;  // overflow still counts -> fallback
}

__device__ __forceinline__ void pushs(unsigned long long key,
                                      unsigned long long* cand, int* cnt, int cap) {
    unsigned m = __activemask();
    int lane   = threadIdx.x & 31;
    int leader = __ffs(m) - 1;
    int rank   = __popc(m & ((1u << lane) - 1u));
    int base   = 0;
    if (lane == leader) base = atomicAdd(cnt, __popc(m));
    base = __shfl_sync(m, base, leader);
    int pos = base + rank;
    if (pos < cap) cand[pos] = key;
}

__device__ __forceinline__ float logit_thr(float te, float w1) {
    float r = __fdividef(te, w1);
    if (r >= 0.999999f) return __int_as_float(0x7f800000);  // +inf: none pass
    float lt = __logf(r) - __logf(1.0f - r) - 1e-3f;        // sigmoid^-1 with slack
    return fmaxf(lt, -20.0f);                               // keep -1e30 sentinel excluded
}

// ======================= Kernel A: weights + threshold (no sort) =========
__global__ __launch_bounds__(NTA)
void kernelA(const float* __restrict__ logits,
             const float* __restrict__ obj,
             const float* __restrict__ unk)
{
    __shared__ float s_w1[NQ];
    __shared__ int   s_cnt;

    const int b   = blockIdx.x;
    const int tid = threadIdx.x;
    const float* lg = logits + (size_t)b * QCN;

    if (tid == 0) g_cnt[b] = 0;
    for (int q = tid; q < NQ; q += NTA) {
        float w  = __expf(-obj[b * NQ + q]);
        float su = sigf(unk[b * NQ + q]);
        float w1 = w * (1.0f - su);
        s_w1[q] = w1;
        g_w1[b * NQ + q] = w1;
        g_w2[b * NQ + q] = w * su;
    }
    __syncthreads();

    // 2048 stratified samples (128 queries x 16 valid classes), kept in regs
    unsigned samp[8];
#pragma unroll
    for (int k = 0; k < 8; k++) {
        int s = tid * 8 + k;
        int q = (s >> 4) * 7 + 3;       // 3..892
        int c = s & 15;
        float v = s_w1[q] * sigf(lg[q * NC + c]);
        samp[k] = __float_as_uint(v);   // positive floats: bit order == value order
    }

    // binary search threshold bits so sample-count lands in [12, 48]
    // (est. total survivors in ~[475, 1900] of 81000)
    unsigned lo = 0, hi = 0x7f800000u, thr = 0;
    bool found = false;
    for (int it = 0; it < 26 && !found && lo < hi; it++) {
        unsigned mid = lo + ((hi - lo) >> 1);
        if (tid == 0) s_cnt = 0;
        __syncthreads();
        int c = 0;
#pragma unroll
        for (int k = 0; k < 8; k++) c += (samp[k] >= mid);
        c = __reduce_add_sync(0xffffffffu, c);
        if ((tid & 31) == 0) atomicAdd(&s_cnt, c);
        __syncthreads();
        int total = s_cnt;
        __syncthreads();
        if (total >= 12 && total <= 48) { thr = mid; found = true; }
        else if (total > 48) lo = mid + 1;
        else hi = mid;
    }
    if (!found) thr = lo;   // may over/under-produce -> kernelC fallback covers

    float thrf = __uint_as_float(thr);
    if (tid == 0) g_thr[b] = thrf;
    float te = thrf * 0.9999f;

    for (int q = tid; q < NQ; q += NTA) {
        g_lthr[b * NQ + q] = logit_thr(te, s_w1[q]);
        float w2 = g_w2[b * NQ + q];
        if (w2 >= te) {
            unsigned i = (unsigned)(q * NC + 80);
            pushg(b, ((unsigned long long)__float_as_uint(w2) << 32) | (~i));
        }
    }
}

// ======================= Kernel B: query-major scan ======================
__global__ __launch_bounds__(NTB)
void kernelB(const float* __restrict__ logits)
{
    const int b    = blockIdx.y;
    const int qb   = blockIdx.x * QPB;
    const int lane = threadIdx.x & 31;
    const int warp = threadIdx.x >> 5;
    const float* lg = logits + (size_t)b * QCN;

    float v0[5], v1[5], lt[5], w1[5];
    int   qv[5];
#pragma unroll
    for (int j = 0; j < 5; j++) {
        int q = qb + warp + 8 * j;           // covers qb..qb+39
        qv[j] = q;
        const float* base = lg + q * NC;
        v0[j] = base[lane];                              // classes 0..31
        v1[j] = (lane < 28) ? base[32 + lane] : -1e30f;  // classes 32..59
        lt[j] = g_lthr[b * NQ + q];
        w1[j] = g_w1[b * NQ + q];
    }
#pragma unroll
    for (int j = 0; j < 5; j++) {
        if (v0[j] >= lt[j]) {
            float p = w1[j] * sigf(v0[j]);
            unsigned i = (unsigned)(qv[j] * NC + lane);
            pushg(b, ((unsigned long long)__float_as_uint(p) << 32) | (~i));
        }
        if (v1[j] >= lt[j]) {
            float p = w1[j] * sigf(v1[j]);
            unsigned i = (unsigned)(qv[j] * NC + 32 + lane);
            pushg(b, ((unsigned long long)__float_as_uint(p) << 32) | (~i));
        }
    }
}

// ======================= Kernel C: select + small sort + emit ============
__global__ __launch_bounds__(NTC)
void kernelC(const float* __restrict__ logits,
             const float* __restrict__ boxes,
             const float* __restrict__ tsizes,
             float* __restrict__ out)
{
    __shared__ unsigned long long s_cand[CAP];    // 32 KB (first 512 reused for small sort)
    __shared__ float s_w1[NQ], s_w2[NQ], s_lthr[NQ];
    __shared__ int   s_cnt;

    const int b   = blockIdx.x;
    const int tid = threadIdx.x;
    const float* lg = logits + (size_t)b * QCN;

    int n = g_cnt[b];
    int n_sort;

    if (n >= TOPK && n <= CAP) {
        // load candidates into registers (strided, coalesced)
        unsigned long long kr[8];
#pragma unroll
        for (int k = 0; k < 8; k++) {
            int t = tid + k * NTC;
            kr[k] = (t < n) ? g_cand[b * CAP + t] : 0ULL;
        }
        // binary search on value bits: exact survivor count in [CLO, CHI]
        unsigned lo = 0, hi = 0x7f800000u, thr2 = 0;
        bool found = false;
        for (int it = 0; it < 30 && !found && lo < hi; it++) {
            unsigned mid = lo + ((hi - lo) >> 1);
            if (tid == 0) s_cnt = 0;
            __syncthreads();
            int c = 0;
#pragma unroll
            for (int k = 0; k < 8; k++) c += ((unsigned)(kr[k] >> 32) >= mid);
            c = __reduce_add_sync(0xffffffffu, c);
            if ((tid & 31) == 0) atomicAdd(&s_cnt, c);
            __syncthreads();
            int total = s_cnt;
            __syncthreads();
            if (total >= CLO && total <= CHI) { thr2 = mid; found = true; }
            else if (total > CHI) lo = mid + 1;
            else hi = mid;
        }
        if (found) {
            if (tid == 0) s_cnt = 0;
            __syncthreads();
#pragma unroll
            for (int k = 0; k < 8; k++)
                if ((unsigned)(kr[k] >> 32) >= thr2)
                    pushs(kr[k], s_cand, &s_cnt, SORTN);
            __syncthreads();
            int n2 = s_cnt;
            for (int t = n2 + tid; t < SORTN; t += NTC) s_cand[t] = 0ULL;
            __syncthreads();
            n_sort = SORTN;
        } else {
            // pathological ties: full sort of all candidates
            for (int t = tid; t < CAP; t += NTC)
                s_cand[t] = (t < n) ? g_cand[b * CAP + t] : 0ULL;
            __syncthreads();
            n_sort = CAP;
        }
    } else {
        // --------- fallback: in-block rescan with threshold retry --------
        for (int q = tid; q < NQ; q += NTC) {
            s_w1[q] = g_w1[b * NQ + q];
            s_w2[q] = g_w2[b * NQ + q];
        }
        __syncthreads();
        float curthr = g_thr[b];
        for (int attempt = 0; attempt < 12; attempt++) {
            if (n < TOPK) curthr *= 0.25f; else curthr *= 4.0f;
            float te = curthr * 0.9999f;
            for (int q = tid; q < NQ; q += NTC)
                s_lthr[q] = logit_thr(te, s_w1[q]);
            if (tid == 0) s_cnt = 0;
            __syncthreads();
            for (int q = tid; q < NQ; q += NTC) {
                if (s_w2[q] >= te) {
                    unsigned i = (unsigned)(q * NC + 80);
                    pushs(((unsigned long long)__float_as_uint(s_w2[q]) << 32) | (~i),
                          s_cand, &s_cnt, CAP);
                }
            }
            for (int i = tid; i < QCN; i += NTC) {
                unsigned q = (unsigned)i / NC;
                int c = i - (int)q * NC;
                if (c < 60) {
                    float v = lg[i];
                    if (v >= s_lthr[q]) {
                        float p = s_w1[q] * sigf(v);
                        pushs(((unsigned long long)__float_as_uint(p) << 32) |
                              (~(unsigned)i), s_cand, &s_cnt, CAP);
                    }
                }
            }
            __syncthreads();
            n = s_cnt;
            if (n >= TOPK && n <= CAP) break;
            __syncthreads();
        }
        if (n > CAP) n = CAP;
        for (int t = n + tid; t < CAP; t += NTC) s_cand[t] = 0ULL;
        __syncthreads();
        n_sort = CAP;
    }

    // bitonic ascending sort of n_sort x u64
    for (int k = 2; k <= n_sort; k <<= 1)
        for (int j = k >> 1; j > 0; j >>= 1) {
            for (int t = tid; t < n_sort; t += NTC) {
                int x = t ^ j;
                if (x > t) {
                    unsigned long long a = s_cand[t], bb = s_cand[x];
                    bool up = ((t & k) == 0);
                    if (up ? (a > bb) : (a < bb)) { s_cand[t] = bb; s_cand[x] = a; }
                }
            }
            __syncthreads();
        }

    // emit top-100 (descending from the back)
    if (tid < TOPK) {
        unsigned long long key = s_cand[n_sort - 1 - tid];
        float v    = __uint_as_float((unsigned)(key >> 32));
        unsigned i = ~(unsigned)key;
        if (key == 0ULL) { v = 0.0f; i = 0; }
        unsigned q = i / NC;
        unsigned c = i - q * NC;
        int o = b * TOPK + tid;
        out[o] = v;                               // scores
        out[NB * TOPK + o] = (float)c;            // labels
        const float* bx = boxes + ((size_t)(b * NQ + q)) * 4;
        float cx = bx[0], cy = bx[1], w = bx[2], h = bx[3];
        float ih = tsizes[b * 2 + 0];
        float iw = tsizes[b * 2 + 1];
        float* ob = out + 2 * NB * TOPK + (size_t)o * 4;  // boxes
        ob[0] = (cx - 0.5f * w) * iw;
        ob[1] = (cy - 0.5f * h) * ih;
        ob[2] = (cx + 0.5f * w) * iw;
        ob[3] = (cy + 0.5f * h) * ih;
    }
}

extern "C" void kernel_launch(void* const* d_in, const int* in_sizes, int n_in,
                              void* d_out, int out_size) {
    const float* logits = (const float*)d_in[0];
    const float* obj    = (const float*)d_in[1];
    const float* boxes  = (const float*)d_in[2];
    const float* unk    = (const float*)d_in[3];
    const float* ts     = (const float*)d_in[4];
    float* out = (float*)d_out;

    kernelA<<<NB, NTA>>>(logits, obj, unk);
    kernelB<<<dim3(SPLITB, NB), NTB>>>(logits);
    kernelC<<<NB, NTC>>>(logits, boxes, ts, out);
}

// round 4
// speedup vs baseline: 2.6375x; 2.6375x over previous
#include <cuda_runtime.h>

#define NB     256
#define NQ     1000
#define NC     81
#define QCN    81000
#define TOPK   100
#define CAP    8192          // global candidate capacity per batch
#define CAPF   4096          // fallback shared capacity
#define NTA    512
#define NTB    256
#define NTC    512
#define QPB    40
#define SPLITB 25
#define SORTN  512
#define SPT    16            // samples per thread (A): 512*16 = 8192 slots, 8000 used
#define CPT    16            // candidates per thread (C): 512*16 = 8192
#define WLO    110           // sample-count window (guarantees >=110 survivors)
#define WHI    220
#define CLO    100           // kernelC refine window
#define CHI    448

// ---- global scratch (no allocs allowed) --------------------------------
__device__ float               g_w1[NB * NQ];
__device__ float               g_w2[NB * NQ];
__device__ float               g_lthr[NB * NQ];
__device__ float               g_thr[NB];
__device__ unsigned long long  g_cand[NB * CAP];
__device__ int                 g_cnt[NB];

__device__ __forceinline__ float sigf(float x) {
    return __fdividef(1.0f, 1.0f + __expf(-x));
}

__device__ __forceinline__ void pushg(int b, unsigned long long key) {
    unsigned m = __activemask();
    int lane   = threadIdx.x & 31;
    int leader = __ffs(m) - 1;
    int rank   = __popc(m & ((1u << lane) - 1u));
    int base   = 0;
    if (lane == leader) base = atomicAdd(&g_cnt[b], __popc(m));
    base = __shfl_sync(m, base, leader);
    int pos = base + rank;
    if (pos < CAP) g_cand[b * CAP + pos] = key;  // overflow counts -> fallback
}

__device__ __forceinline__ void pushs(unsigned long long key,
                                      unsigned long long* cand, int* cnt, int cap) {
    unsigned m = __activemask();
    int lane   = threadIdx.x & 31;
    int leader = __ffs(m) - 1;
    int rank   = __popc(m & ((1u << lane) - 1u));
    int base   = 0;
    if (lane == leader) base = atomicAdd(cnt, __popc(m));
    base = __shfl_sync(m, base, leader);
    int pos = base + rank;
    if (pos < cap) cand[pos] = key;
}

__device__ __forceinline__ float logit_thr(float te, float w1) {
    float r = __fdividef(te, w1);
    if (r >= 0.999999f) return __int_as_float(0x7f800000);  // +inf: none pass
    float lt = __logf(r) - __logf(1.0f - r) - 1e-3f;        // sigmoid^-1 with slack
    return fmaxf(lt, -20.0f);   // real logits ~N(0,1) all > -20: no exclusion
}

// ======================= Kernel A: weights + threshold ===================
__global__ __launch_bounds__(NTA)
void kernelA(const float* __restrict__ logits,
             const float* __restrict__ obj,
             const float* __restrict__ unk)
{
    __shared__ float s_w1[NQ];
    __shared__ int   s_it[36];

    const int b   = blockIdx.x;
    const int tid = threadIdx.x;
    const float* lg = logits + (size_t)b * QCN;

    if (tid < 36) s_it[tid] = 0;
    if (tid == 0) g_cnt[b] = 0;
    for (int q = tid; q < NQ; q += NTA) {
        float w  = __expf(-obj[b * NQ + q]);
        float su = sigf(unk[b * NQ + q]);
        float w1 = w * (1.0f - su);
        s_w1[q] = w1;
        g_w1[b * NQ + q] = w1;
        g_w2[b * NQ + q] = w * su;
    }
    __syncthreads();

    // 8000 samples: EVERY query x classes 0..7 (coalesced: s = k*512 + tid)
    unsigned samp[SPT];
#pragma unroll
    for (int k = 0; k < SPT; k++) {
        int s = k * NTA + tid;
        int q = s >> 3;
        int c = s & 7;
        samp[k] = (q < NQ) ? __float_as_uint(s_w1[q] * sigf(lg[q * NC + c]))
                           : 0u;
    }

    // bit-bisection: sample-count in [WLO, WHI] -> survivors in ~[110, 1650]
    unsigned lo = 0, hi = 0x7f800000u, thr = 0;
    bool found = false;
    for (int it = 0; it < 32 && !found && lo < hi; it++) {
        unsigned mid = lo + ((hi - lo) >> 1);
        int c = 0;
#pragma unroll
        for (int k = 0; k < SPT; k++) c += (samp[k] >= mid);
        c = __reduce_add_sync(0xffffffffu, c);
        if ((tid & 31) == 0) atomicAdd(&s_it[it], c);
        __syncthreads();
        int total = s_it[it];
        if (total >= WLO && total <= WHI) { thr = mid; found = true; }
        else if (total > WHI) lo = mid + 1;
        else hi = mid;
    }
    if (!found) thr = lo;

    float thrf = __uint_as_float(thr);
    if (tid == 0) g_thr[b] = thrf;
    float te = thrf * 0.9999f;

    for (int q = tid; q < NQ; q += NTA) {
        g_lthr[b * NQ + q] = logit_thr(te, s_w1[q]);
        float w2 = g_w2[b * NQ + q];
        if (w2 >= te) {
            unsigned i = (unsigned)(q * NC + 80);
            pushg(b, ((unsigned long long)__float_as_uint(w2) << 32) | (~i));
        }
    }
}

// ======================= Kernel B: query-major scan ======================
__global__ __launch_bounds__(NTB)
void kernelB(const float* __restrict__ logits)
{
    const int b    = blockIdx.y;
    const int qb   = blockIdx.x * QPB;
    const int lane = threadIdx.x & 31;
    const int warp = threadIdx.x >> 5;
    const float* lg = logits + (size_t)b * QCN;

    float v0[5], v1[5], lt[5], w1[5];
    int   qv[5];
#pragma unroll
    for (int j = 0; j < 5; j++) {
        int q = qb + warp + 8 * j;
        qv[j] = q;
        const float* base = lg + q * NC;
        v0[j] = base[lane];                              // classes 0..31
        v1[j] = (lane < 28) ? base[32 + lane] : -1e30f;  // classes 32..59
        lt[j] = g_lthr[b * NQ + q];
        w1[j] = g_w1[b * NQ + q];
    }
#pragma unroll
    for (int j = 0; j < 5; j++) {
        if (v0[j] >= lt[j]) {
            float p = w1[j] * sigf(v0[j]);
            unsigned i = (unsigned)(qv[j] * NC + lane);
            pushg(b, ((unsigned long long)__float_as_uint(p) << 32) | (~i));
        }
        if (v1[j] >= lt[j]) {
            float p = w1[j] * sigf(v1[j]);
            unsigned i = (unsigned)(qv[j] * NC + 32 + lane);
            pushg(b, ((unsigned long long)__float_as_uint(p) << 32) | (~i));
        }
    }
}

// ======================= Kernel C: refine + small sort + emit ============
__global__ __launch_bounds__(NTC)
void kernelC(const float* __restrict__ logits,
             const float* __restrict__ boxes,
             const float* __restrict__ tsizes,
             float* __restrict__ out)
{
    __shared__ unsigned long long s_cand[CAPF];   // 32 KB
    __shared__ float s_w1[NQ], s_w2[NQ], s_lthr[NQ];
    __shared__ int   s_it[36];
    __shared__ int   s_cnt;

    const int b   = blockIdx.x;
    const int tid = threadIdx.x;
    const float* lg = logits + (size_t)b * QCN;

    if (tid < 36) s_it[tid] = 0;
    int n = g_cnt[b];
    __syncthreads();

    int n_sort;
    if (n >= TOPK && n <= CAP) {
        // ---- normal path (guaranteed by construction) -------------------
        unsigned long long kr[CPT];
#pragma unroll
        for (int k = 0; k < CPT; k++) {
            int t = tid + k * NTC;
            kr[k] = (t < n) ? g_cand[b * CAP + t] : 0ULL;
        }
        // exact bit-bisection on values: survivor count in [CLO, CHI]
        unsigned lo = 0, hi = 0x7f800000u, thr2 = 0;
        bool found = false;
        for (int it = 0; it < 32 && !found && lo < hi; it++) {
            unsigned mid = lo + ((hi - lo) >> 1);
            int c = 0;
#pragma unroll
            for (int k = 0; k < CPT; k++) c += ((unsigned)(kr[k] >> 32) >= mid);
            c = __reduce_add_sync(0xffffffffu, c);
            if ((tid & 31) == 0) atomicAdd(&s_it[it], c);
            __syncthreads();
            int total = s_it[it];
            if (total >= CLO && total <= CHI) { thr2 = mid; found = true; }
            else if (total > CHI) lo = mid + 1;
            else hi = mid;
        }
        if (found) {
            if (tid == 0) s_cnt = 0;
            __syncthreads();
#pragma unroll
            for (int k = 0; k < CPT; k++)
                if ((unsigned)(kr[k] >> 32) >= thr2)
                    pushs(kr[k], s_cand, &s_cnt, SORTN);
            __syncthreads();
            for (int t = s_cnt + tid; t < SORTN; t += NTC) s_cand[t] = 0ULL;
            __syncthreads();
            n_sort = SORTN;
        } else {
            // mass-tie pathology (unreachable with continuous data)
            int m = (n < CAPF) ? n : CAPF;
            for (int t = tid; t < CAPF; t += NTC)
                s_cand[t] = (t < m) ? g_cand[b * CAP + t] : 0ULL;
            __syncthreads();
            n_sort = CAPF;
        }
    } else {
        // ---- dead-code fallback: bounded rescan with retry --------------
        for (int q = tid; q < NQ; q += NTC) {
            s_w1[q] = g_w1[b * NQ + q];
            s_w2[q] = g_w2[b * NQ + q];
        }
        __syncthreads();
        float curthr = g_thr[b];
        for (int attempt = 0; attempt < 12; attempt++) {
            if (n < TOPK) curthr *= 0.25f; else curthr *= 4.0f;
            float te = curthr * 0.9999f;
            for (int q = tid; q < NQ; q += NTC)
                s_lthr[q] = logit_thr(te, s_w1[q]);
            if (tid == 0) s_cnt = 0;
            __syncthreads();
            for (int q = tid; q < NQ; q += NTC) {
                if (s_w2[q] >= te) {
                    unsigned i = (unsigned)(q * NC + 80);
                    pushs(((unsigned long long)__float_as_uint(s_w2[q]) << 32) | (~i),
                          s_cand, &s_cnt, CAPF);
                }
            }
            for (int i = tid; i < QCN; i += NTC) {
                unsigned q = (unsigned)i / NC;
                int c = i - (int)q * NC;
                if (c < 60) {
                    float v = lg[i];
                    if (v >= s_lthr[q]) {
                        float p = s_w1[q] * sigf(v);
                        pushs(((unsigned long long)__float_as_uint(p) << 32) |
                              (~(unsigned)i), s_cand, &s_cnt, CAPF);
                    }
                }
            }
            __syncthreads();
            n = s_cnt;
            if (n >= TOPK && n <= CAPF) break;
            __syncthreads();
        }
        if (n > CAPF) n = CAPF;
        for (int t = n + tid; t < CAPF; t += NTC) s_cand[t] = 0ULL;
        __syncthreads();
        n_sort = CAPF;
    }

    // bitonic ascending sort of n_sort x u64
    for (int k = 2; k <= n_sort; k <<= 1)
        for (int j = k >> 1; j > 0; j >>= 1) {
            for (int t = tid; t < n_sort; t += NTC) {
                int x = t ^ j;
                if (x > t) {
                    unsigned long long a = s_cand[t], bb = s_cand[x];
                    bool up = ((t & k) == 0);
                    if (up ? (a > bb) : (a < bb)) { s_cand[t] = bb; s_cand[x] = a; }
                }
            }
            __syncthreads();
        }

    // emit top-100 (descending from the back)
    if (tid < TOPK) {
        unsigned long long key = s_cand[n_sort - 1 - tid];
        float v    = __uint_as_float((unsigned)(key >> 32));
        unsigned i = ~(unsigned)key;
        if (key == 0ULL) { v = 0.0f; i = 0; }
        unsigned q = i / NC;
        unsigned c = i - q * NC;
        int o = b * TOPK + tid;
        out[o] = v;                               // scores
        out[NB * TOPK + o] = (float)c;            // labels
        const float* bx = boxes + ((size_t)(b * NQ + q)) * 4;
        float cx = bx[0], cy = bx[1], w = bx[2], h = bx[3];
        float ih = tsizes[b * 2 + 0];
        float iw = tsizes[b * 2 + 1];
        float* ob = out + 2 * NB * TOPK + (size_t)o * 4;  // boxes
        ob[0] = (cx - 0.5f * w) * iw;
        ob[1] = (cy - 0.5f * h) * ih;
        ob[2] = (cx + 0.5f * w) * iw;
        ob[3] = (cy + 0.5f * h) * ih;
    }
}

extern "C" void kernel_launch(void* const* d_in, const int* in_sizes, int n_in,
                              void* d_out, int out_size) {
    const float* logits = (const float*)d_in[0];
    const float* obj    = (const float*)d_in[1];
    const float* boxes  = (const float*)d_in[2];
    const float* unk    = (const float*)d_in[3];
    const float* ts     = (const float*)d_in[4];
    float* out = (float*)d_out;

    kernelA<<<NB, NTA>>>(logits, obj, unk);
    kernelB<<<dim3(SPLITB, NB), NTB>>>(logits);
    kernelC<<<NB, NTC>>>(logits, boxes, ts, out);
}

// round 5
// speedup vs baseline: 2.9316x; 1.1115x over previous
#include <cuda_runtime.h>

#define NB     256
#define NQ     1000
#define NC     81
#define QCN    81000
#define TOPK   100
#define CAP    8192          // global candidate capacity per batch
#define CAPF   4096          // fallback shared capacity
#define NTA    512
#define NTB    256
#define NTC    512
#define QPB    40
#define SPLITB 25
#define NSAMP  4000          // every query x classes 0..3
#define WLO    110           // sample suffix-count floor (guarantees >=110 survivors)
#define CPT    16            // candidates per thread (C): 512*16 = 8192
#define NBIN   4096
#define SORTN  256

// ---- global scratch (no allocs allowed) --------------------------------
__device__ float               g_w1[NB * NQ];
__device__ float               g_w2[NB * NQ];
__device__ float               g_lthr[NB * NQ];
__device__ float               g_thr[NB];
__device__ unsigned            g_thrbits[NB];
__device__ unsigned long long  g_cand[NB * CAP];
__device__ int                 g_cnt[NB];

__device__ __forceinline__ float sigf(float x) {
    return __fdividef(1.0f, 1.0f + __expf(-x));
}

__device__ __forceinline__ void pushg(int b, unsigned long long key) {
    unsigned m = __activemask();
    int lane   = threadIdx.x & 31;
    int leader = __ffs(m) - 1;
    int rank   = __popc(m & ((1u << lane) - 1u));
    int base   = 0;
    if (lane == leader) base = atomicAdd(&g_cnt[b], __popc(m));
    base = __shfl_sync(m, base, leader);
    int pos = base + rank;
    if (pos < CAP) g_cand[b * CAP + pos] = key;  // overflow counts -> fallback
}

__device__ __forceinline__ void pushs(unsigned long long key,
                                      unsigned long long* cand, int* cnt, int cap) {
    unsigned m = __activemask();
    int lane   = threadIdx.x & 31;
    int leader = __ffs(m) - 1;
    int rank   = __popc(m & ((1u << lane) - 1u));
    int base   = 0;
    if (lane == leader) base = atomicAdd(cnt, __popc(m));
    base = __shfl_sync(m, base, leader);
    int pos = base + rank;
    if (pos < cap) cand[pos] = key;
}

__device__ __forceinline__ float logit_thr(float te, float w1) {
    float r = __fdividef(te, w1);
    if (r >= 0.999999f) return __int_as_float(0x7f800000);  // +inf: none pass
    float lt = __logf(r) - __logf(1.0f - r) - 1e-3f;        // sigmoid^-1 with slack
    return fmaxf(lt, -20.0f);
}

// two-level suffix-crossing search shared by A and C:
// given per-thread 8 bin counts (bins t*8..t*8+7), find largest bin with
// suffix_cum >= target. Writes (bin, cum) to s_out[0], s_out[1].
__device__ __forceinline__ void suffix_find(const int* binv, int cs, int target,
                                            int* s_wsum, int* s_out,
                                            const int* hist_unused) {
    int tid  = threadIdx.x;
    int lane = tid & 31;
    int w    = tid >> 5;
    // warp inclusive suffix over lanes (higher lane = higher bins)
    int suf = cs;
#pragma unroll
    for (int off = 1; off < 32; off <<= 1) {
        int v = __shfl_down_sync(0xffffffffu, suf, off);
        if (lane + off < 32) suf += v;
    }
    if (lane == 0) s_wsum[w] = suf;     // warp total
    __syncthreads();
    int wsuf = 0;
    for (int w2 = w + 1; w2 < 16; w2++) wsuf += s_wsum[w2];
    int sufExcl = wsuf + (suf - cs);    // strictly above this thread's bins
    if (sufExcl < target && sufExcl + cs >= target) {
        int run = sufExcl;
#pragma unroll
        for (int k = 7; k >= 0; k--) {
            run += binv[k];
            if (run >= target) { s_out[0] = tid * 8 + k; s_out[1] = run; break; }
        }
    }
    __syncthreads();
}

// ======================= Kernel A: weights + threshold ===================
__global__ __launch_bounds__(NTA)
void kernelA(const float* __restrict__ logits,
             const float* __restrict__ obj,
             const float* __restrict__ unk)
{
    __shared__ float s_w1[NQ];
    __shared__ int   s_hist[NBIN];       // 16 KB
    __shared__ int   s_wsum[16];
    __shared__ int   s_out[2];

    const int b   = blockIdx.x;
    const int tid = threadIdx.x;
    const float* lg = logits + (size_t)b * QCN;

    if (tid == 0) g_cnt[b] = 0;
#pragma unroll
    for (int k = 0; k < NBIN / NTA; k++) s_hist[k * NTA + tid] = 0;
    for (int q = tid; q < NQ; q += NTA) {
        float w  = __expf(-obj[b * NQ + q]);
        float su = sigf(unk[b * NQ + q]);
        float w1 = w * (1.0f - su);
        s_w1[q] = w1;
        g_w1[b * NQ + q] = w1;
        g_w2[b * NQ + q] = w * su;
    }
    __syncthreads();

    // histogram 4000 samples (every query x classes 0..3)
#pragma unroll
    for (int k = 0; k < 8; k++) {
        int s = k * NTA + tid;
        if (s < NSAMP) {
            int q = s >> 2;
            int c = s & 3;
            float v = s_w1[q] * sigf(lg[q * NC + c]);
            unsigned idx = __float_as_uint(v) >> 19;   // exp + 4 mantissa bits
            if (idx > NBIN - 1) idx = NBIN - 1;
            atomicAdd(&s_hist[idx], 1);
        }
    }
    __syncthreads();

    // find largest bin with suffix count >= WLO
    int binv[8], cs = 0;
    int t8 = tid * 8;
#pragma unroll
    for (int k = 0; k < 8; k++) { binv[k] = s_hist[t8 + k]; cs += binv[k]; }
    suffix_find(binv, cs, WLO, s_wsum, s_out, s_hist);

    unsigned thrbits = (unsigned)s_out[0] << 19;
    float thrf = __uint_as_float(thrbits);
    if (tid == 0) { g_thr[b] = thrf; g_thrbits[b] = thrbits; }
    float te = thrf * 0.9999f;

    for (int q = tid; q < NQ; q += NTA) {
        g_lthr[b * NQ + q] = logit_thr(te, s_w1[q]);
        float w2 = g_w2[b * NQ + q];
        if (w2 >= te) {
            unsigned i = (unsigned)(q * NC + 80);
            pushg(b, ((unsigned long long)__float_as_uint(w2) << 32) | (~i));
        }
    }
}

// ======================= Kernel B: query-major scan ======================
__global__ __launch_bounds__(NTB)
void kernelB(const float* __restrict__ logits)
{
    const int b    = blockIdx.y;
    const int qb   = blockIdx.x * QPB;
    const int lane = threadIdx.x & 31;
    const int warp = threadIdx.x >> 5;
    const float* lg = logits + (size_t)b * QCN;

    float v0[5], v1[5], lt[5];
    int   qv[5];
#pragma unroll
    for (int j = 0; j < 5; j++) {
        int q = qb + warp + 8 * j;
        qv[j] = q;
        const float* base = lg + q * NC;
        v0[j] = base[lane];                              // classes 0..31
        v1[j] = (lane < 28) ? base[32 + lane] : -1e30f;  // classes 32..59
        lt[j] = g_lthr[b * NQ + q];
    }
#pragma unroll
    for (int j = 0; j < 5; j++) {
        if (v0[j] >= lt[j]) {
            float p = g_w1[b * NQ + qv[j]] * sigf(v0[j]);
            unsigned i = (unsigned)(qv[j] * NC + lane);
            pushg(b, ((unsigned long long)__float_as_uint(p) << 32) | (~i));
        }
        if (v1[j] >= lt[j]) {
            float p = g_w1[b * NQ + qv[j]] * sigf(v1[j]);
            unsigned i = (unsigned)(qv[j] * NC + 32 + lane);
            pushg(b, ((unsigned long long)__float_as_uint(p) << 32) | (~i));
        }
    }
}

// ======================= Kernel C: refine + small sort + emit ============
__global__ __launch_bounds__(NTC)
void kernelC(const float* __restrict__ logits,
             const float* __restrict__ boxes,
             const float* __restrict__ tsizes,
             float* __restrict__ out)
{
    __shared__ unsigned long long s_cand[CAPF];   // 32 KB; upper 16 KB aliased as hist
    __shared__ float s_w1[NQ], s_w2[NQ], s_lthr[NQ];
    __shared__ int   s_wsum[16];
    __shared__ int   s_out[2];
    __shared__ int   s_cnt;

    int* s_hist = (int*)(s_cand + 2048);          // 4096 ints in upper half

    const int b   = blockIdx.x;
    const int tid = threadIdx.x;
    const float* lg = logits + (size_t)b * QCN;

    int n = g_cnt[b];
    int n_sort;

    if (n >= TOPK && n <= CAP) {
        // ---- normal path ------------------------------------------------
        unsigned long long kr[CPT];
#pragma unroll
        for (int k = 0; k < CPT; k++) {
            int t = tid + k * NTC;
            kr[k] = (t < n) ? g_cand[b * CAP + t] : 0ULL;
        }
#pragma unroll
        for (int k = 0; k < NBIN / NTC; k++) s_hist[k * NTC + tid] = 0;
        __syncthreads();

        unsigned base = g_thrbits[b] >> 16;       // fine-bin base
#pragma unroll
        for (int k = 0; k < CPT; k++) {
            if (tid + k * NTC < n) {
                int idx = (int)((unsigned)(kr[k] >> 32) >> 16) - (int)base;
                idx = (idx < 0) ? 0 : ((idx > NBIN - 1) ? NBIN - 1 : idx);
                atomicAdd(&s_hist[idx], 1);
            }
        }
        __syncthreads();

        int binv[8], cs = 0;
        int t8 = tid * 8;
#pragma unroll
        for (int k = 0; k < 8; k++) { binv[k] = s_hist[t8 + k]; cs += binv[k]; }
        suffix_find(binv, cs, TOPK, s_wsum, s_out, s_hist);

        int bin2 = s_out[0];
        int cum  = s_out[1];
        if (cum <= SORTN) {
            unsigned thr2 = (bin2 == 0) ? 0u : ((base + (unsigned)bin2) << 16);
            if (tid == 0) s_cnt = 0;
            __syncthreads();
#pragma unroll
            for (int k = 0; k < CPT; k++) {
                if (tid + k * NTC < n && (unsigned)(kr[k] >> 32) >= thr2)
                    pushs(kr[k], s_cand, &s_cnt, SORTN);
            }
            __syncthreads();
            for (int t = s_cnt + tid; t < SORTN; t += NTC) s_cand[t] = 0ULL;
            __syncthreads();
            n_sort = SORTN;
        } else {
            // tie pathology: full sort of candidates
            int m = (n < CAPF) ? n : CAPF;
            __syncthreads();
            for (int t = tid; t < CAPF; t += NTC)
                s_cand[t] = (t < m) ? g_cand[b * CAP + t] : 0ULL;
            __syncthreads();
            n_sort = CAPF;
        }
    } else {
        // ---- fallback: bounded rescan with retry (dead in practice) -----
        for (int q = tid; q < NQ; q += NTC) {
            s_w1[q] = g_w1[b * NQ + q];
            s_w2[q] = g_w2[b * NQ + q];
        }
        __syncthreads();
        float curthr = g_thr[b];
        if (curthr <= 0.0f) curthr = 1e-6f;
        for (int attempt = 0; attempt < 12; attempt++) {
            if (n < TOPK) curthr *= 0.25f; else curthr *= 4.0f;
            float te = curthr * 0.9999f;
            for (int q = tid; q < NQ; q += NTC)
                s_lthr[q] = logit_thr(te, s_w1[q]);
            if (tid == 0) s_cnt = 0;
            __syncthreads();
            for (int q = tid; q < NQ; q += NTC) {
                if (s_w2[q] >= te) {
                    unsigned i = (unsigned)(q * NC + 80);
                    pushs(((unsigned long long)__float_as_uint(s_w2[q]) << 32) | (~i),
                          s_cand, &s_cnt, CAPF);
                }
            }
            for (int i = tid; i < QCN; i += NTC) {
                unsigned q = (unsigned)i / NC;
                int c = i - (int)q * NC;
                if (c < 60) {
                    float v = lg[i];
                    if (v >= s_lthr[q]) {
                        float p = s_w1[q] * sigf(v);
                        pushs(((unsigned long long)__float_as_uint(p) << 32) |
                              (~(unsigned)i), s_cand, &s_cnt, CAPF);
                    }
                }
            }
            __syncthreads();
            n = s_cnt;
            if (n >= TOPK && n <= CAPF) break;
            __syncthreads();
        }
        if (n > CAPF) n = CAPF;
        for (int t = n + tid; t < CAPF; t += NTC) s_cand[t] = 0ULL;
        __syncthreads();
        n_sort = CAPF;
    }

    // bitonic ascending sort of n_sort x u64
    for (int k = 2; k <= n_sort; k <<= 1)
        for (int j = k >> 1; j > 0; j >>= 1) {
            for (int t = tid; t < n_sort; t += NTC) {
                int x = t ^ j;
                if (x > t) {
                    unsigned long long a = s_cand[t], bb = s_cand[x];
                    bool up = ((t & k) == 0);
                    if (up ? (a > bb) : (a < bb)) { s_cand[t] = bb; s_cand[x] = a; }
                }
            }
            __syncthreads();
        }

    // emit top-100 (descending from the back)
    if (tid < TOPK) {
        unsigned long long key = s_cand[n_sort - 1 - tid];
        float v    = __uint_as_float((unsigned)(key >> 32));
        unsigned i = ~(unsigned)key;
        if (key == 0ULL) { v = 0.0f; i = 0; }
        unsigned q = i / NC;
        unsigned c = i - q * NC;
        int o = b * TOPK + tid;
        out[o] = v;                               // scores
        out[NB * TOPK + o] = (float)c;            // labels
        const float* bx = boxes + ((size_t)(b * NQ + q)) * 4;
        float cx = bx[0], cy = bx[1], w = bx[2], h = bx[3];
        float ih = tsizes[b * 2 + 0];
        float iw = tsizes[b * 2 + 1];
        float* ob = out + 2 * NB * TOPK + (size_t)o * 4;  // boxes
        ob[0] = (cx - 0.5f * w) * iw;
        ob[1] = (cy - 0.5f * h) * ih;
        ob[2] = (cx + 0.5f * w) * iw;
        ob[3] = (cy + 0.5f * h) * ih;
    }
}

extern "C" void kernel_launch(void* const* d_in, const int* in_sizes, int n_in,
                              void* d_out, int out_size) {
    const float* logits = (const float*)d_in[0];
    const float* obj    = (const float*)d_in[1];
    const float* boxes  = (const float*)d_in[2];
    const float* unk    = (const float*)d_in[3];
    const float* ts     = (const float*)d_in[4];
    float* out = (float*)d_out;

    kernelA<<<NB, NTA>>>(logits, obj, unk);
    kernelB<<<dim3(SPLITB, NB), NTB>>>(logits);
    kernelC<<<NB, NTC>>>(logits, boxes, ts, out);
}